// round 3
// baseline (speedup 1.0000x reference)
#include <cuda_runtime.h>

// ---------------------------------------------------------------------------
// LossRecovery: dual channel-attention (spatial + temporal) over (2,8,64,64,256)
//
// All matmuls expressed as two kernels:
//   gemm_nt: C[n,d] = sum_k A[n,k]*B[d,k]   (K fixed = 256)   -- convs + out-GEMMs
//   gemm_tn: S[c,d] = sum_s Q[s,c]*K[s,d]   (K = 4096)        -- attention scores
// plus a warp-per-row softmax.
//
// Input order (metadata.txt = setup_inputs dict order):
//   0:x 1:mask 2:spatial_correction_matrix
//   3:sq_w 4:sq_b 5:sk_w 6:sk_b 7:sv_w 8:sv_b
//   9:tq_w 10:tq_b 11:tk_w 12:tk_b 13:tv_w 14:tv_b
//   15:s_gamma 16:t_gamma
// ---------------------------------------------------------------------------

__device__ float g_q[16L * 4096 * 256];      // 64 MB scratch
__device__ float g_k[16L * 4096 * 256];
__device__ float g_v[16L * 4096 * 256];
__device__ float g_attn[16L * 256 * 256];    // 4 MB

// MODE 0: identity      out[(z*M+n)*256 + d]
// MODE 1: spatial-T     s' = (s%64)*64 + s/64   (tk path)
// MODE 2: v2 scatter    b2 = (bl/8)*8 + d/32 ; d2 = (d%32)*8 + (bl%8)   (tv path)
template <int MODE, bool HAS_BIAS, bool HAS_RES>
__global__ __launch_bounds__(256) void gemm_nt(
    const float* __restrict__ A, int lda, long aBatch,
    const float* __restrict__ B, long bBatch,
    const float* __restrict__ bias,
    const float* __restrict__ gammaPtr,
    const float* __restrict__ res, int ldr,
    float* __restrict__ out, int M)
{
    __shared__ float As[16][128];
    __shared__ float Bs[16][128];

    const int tid = threadIdx.x;
    const int z = blockIdx.z;
    const float* Ab = A + (long)z * aBatch;
    const float* Bb = B + (long)z * bBatch;
    const int row0 = blockIdx.x * 128;
    const int col0 = blockIdx.y * 128;

    const int lr = tid >> 1;          // 0..127
    const int lk = (tid & 1) * 8;     // 0 or 8

    float acc[8][8];
#pragma unroll
    for (int i = 0; i < 8; i++)
#pragma unroll
        for (int j = 0; j < 8; j++) acc[i][j] = 0.f;

    const int ty = tid >> 4;          // 0..15
    const int tx = tid & 15;          // 0..15

    for (int kt = 0; kt < 256; kt += 16) {
#pragma unroll
        for (int i = 0; i < 8; i++)
            As[lk + i][lr] = Ab[(long)(row0 + lr) * lda + kt + lk + i];
#pragma unroll
        for (int i = 0; i < 8; i++)
            Bs[lk + i][lr] = Bb[(long)(col0 + lr) * 256 + kt + lk + i];
        __syncthreads();

#pragma unroll
        for (int kk = 0; kk < 16; kk++) {
            float a[8], b[8];
#pragma unroll
            for (int i = 0; i < 8; i++) a[i] = As[kk][ty * 8 + i];
#pragma unroll
            for (int j = 0; j < 8; j++) b[j] = Bs[kk][tx * 8 + j];
#pragma unroll
            for (int i = 0; i < 8; i++)
#pragma unroll
                for (int j = 0; j < 8; j++) acc[i][j] += a[i] * b[j];
        }
        __syncthreads();
    }

    float gamma = 0.f;
    if (HAS_RES) gamma = *gammaPtr;

#pragma unroll
    for (int i = 0; i < 8; i++) {
        const int n = row0 + ty * 8 + i;
        const long gRow = (long)z * M + n;
#pragma unroll
        for (int j = 0; j < 8; j++) {
            const int d = col0 + tx * 8 + j;
            float val = acc[i][j];
            if (HAS_BIAS) val += bias[d];
            if (HAS_RES) val = gamma * val + res[gRow * (long)ldr + d];

            long idx;
            if (MODE == 0) {
                idx = gRow * 256 + d;
            } else if (MODE == 1) {
                const long bl = gRow >> 12;
                const int s = (int)(gRow & 4095);
                const int s2 = ((s & 63) << 6) | (s >> 6);
                idx = ((bl << 12) + s2) * 256 + d;
            } else {
                const long bl = gRow >> 12;
                const int s = (int)(gRow & 4095);
                const int b = (int)(bl >> 3), l = (int)(bl & 7);
                const int b2 = b * 8 + (d >> 5);
                const int d2 = ((d & 31) << 3) | l;
                idx = ((long)b2 * 4096 + s) * 256 + d2;
            }
            out[idx] = val;
        }
    }
}

// S[z][c][d] = sum_s Q[z][s][c] * K[z][s][d];   M=N=256, Kdim=4096
__global__ __launch_bounds__(256) void gemm_tn(
    const float* __restrict__ Q, const float* __restrict__ K,
    float* __restrict__ S)
{
    __shared__ float Qs[32][64];
    __shared__ float Ks[32][64];

    const int z = blockIdx.z;
    const float* Qb = Q + (long)z * 4096 * 256;
    const float* Kb = K + (long)z * 4096 * 256;
    const int c0 = blockIdx.x * 64;
    const int d0 = blockIdx.y * 64;
    const int tid = threadIdx.x;

    const int sr = tid >> 3;          // 0..31
    const int cc = (tid & 7) * 8;     // 0..56

    float acc[4][4];
#pragma unroll
    for (int i = 0; i < 4; i++)
#pragma unroll
        for (int j = 0; j < 4; j++) acc[i][j] = 0.f;

    const int ty = tid >> 4;
    const int tx = tid & 15;

    for (int st = 0; st < 4096; st += 32) {
#pragma unroll
        for (int i = 0; i < 8; i++)
            Qs[sr][cc + i] = Qb[(long)(st + sr) * 256 + c0 + cc + i];
#pragma unroll
        for (int i = 0; i < 8; i++)
            Ks[sr][cc + i] = Kb[(long)(st + sr) * 256 + d0 + cc + i];
        __syncthreads();

#pragma unroll
        for (int kk = 0; kk < 32; kk++) {
            float a[4], b[4];
#pragma unroll
            for (int i = 0; i < 4; i++) a[i] = Qs[kk][ty * 4 + i];
#pragma unroll
            for (int j = 0; j < 4; j++) b[j] = Ks[kk][tx * 4 + j];
#pragma unroll
            for (int i = 0; i < 4; i++)
#pragma unroll
                for (int j = 0; j < 4; j++) acc[i][j] += a[i] * b[j];
        }
        __syncthreads();
    }

    float* Sb = S + (long)z * 65536;
#pragma unroll
    for (int i = 0; i < 4; i++)
#pragma unroll
        for (int j = 0; j < 4; j++)
            Sb[(long)(c0 + ty * 4 + i) * 256 + d0 + tx * 4 + j] = acc[i][j];
}

// row-wise softmax over 256 elements; 4096 rows, one warp per row
__global__ __launch_bounds__(256) void softmax_rows(float* __restrict__ data)
{
    const int row = blockIdx.x * 8 + (threadIdx.x >> 5);
    const int lane = threadIdx.x & 31;
    float* p = data + (long)row * 256;

    float v[8];
    float m = -1e30f;
#pragma unroll
    for (int i = 0; i < 8; i++) {
        v[i] = p[i * 32 + lane];
        m = fmaxf(m, v[i]);
    }
#pragma unroll
    for (int o = 16; o; o >>= 1) m = fmaxf(m, __shfl_xor_sync(0xffffffffu, m, o));

    float s = 0.f;
#pragma unroll
    for (int i = 0; i < 8; i++) {
        v[i] = __expf(v[i] - m);
        s += v[i];
    }
#pragma unroll
    for (int o = 16; o; o >>= 1) s += __shfl_xor_sync(0xffffffffu, s, o);

    const float inv = 1.f / s;
#pragma unroll
    for (int i = 0; i < 8; i++) p[i * 32 + lane] = v[i] * inv;
}

extern "C" void kernel_launch(void* const* d_in, const int* in_sizes, int n_in,
                              void* d_out, int out_size)
{
    const float* x       = (const float*)d_in[0];
    // d_in[1] = mask (unused), d_in[2] = spatial_correction_matrix (unused)
    const float* sq_w    = (const float*)d_in[3];
    const float* sq_b    = (const float*)d_in[4];
    const float* sk_w    = (const float*)d_in[5];
    const float* sk_b    = (const float*)d_in[6];
    const float* sv_w    = (const float*)d_in[7];
    const float* sv_b    = (const float*)d_in[8];
    const float* tq_w    = (const float*)d_in[9];
    const float* tq_b    = (const float*)d_in[10];
    const float* tk_w    = (const float*)d_in[11];
    const float* tk_b    = (const float*)d_in[12];
    const float* tv_w    = (const float*)d_in[13];
    const float* tv_b    = (const float*)d_in[14];
    const float* s_gamma = (const float*)d_in[15];
    const float* t_gamma = (const float*)d_in[16];
    float* out = (float*)d_out;

    float *q, *k, *v, *attn;
    cudaGetSymbolAddress((void**)&q, g_q);
    cudaGetSymbolAddress((void**)&k, g_k);
    cudaGetSymbolAddress((void**)&v, g_v);
    cudaGetSymbolAddress((void**)&attn, g_attn);

    const dim3 convGrid(512, 2, 1);   // M=65536, N=256
    const dim3 tnGrid(4, 4, 16);      // 256x256 per batch, 16 batches
    const dim3 outGrid(32, 2, 16);    // M=4096, N=256, 16 batches

    // ---- spatial attention ----
    gemm_nt<0, true,  false><<<convGrid, 256>>>(x, 259, 0, sq_w, 0, sq_b, nullptr, nullptr, 0, q, 65536);
    gemm_nt<0, true,  false><<<convGrid, 256>>>(x, 259, 0, sk_w, 0, sk_b, nullptr, nullptr, 0, k, 65536);
    gemm_nt<0, true,  false><<<convGrid, 256>>>(x, 259, 0, sv_w, 0, sv_b, nullptr, nullptr, 0, v, 65536);
    gemm_tn<<<tnGrid, 256>>>(q, k, attn);
    softmax_rows<<<512, 256>>>(attn);
    // x1 = s_gamma*out + x_s  -> stored in d_out
    gemm_nt<0, false, true><<<outGrid, 256>>>(v, 256, 4096L * 256, attn, 65536L,
                                              nullptr, s_gamma, x, 259, out, 4096);

    // ---- temporal attention ----
    gemm_nt<0, true,  false><<<convGrid, 256>>>(out, 256, 0, tq_w, 0, tq_b, nullptr, nullptr, 0, q, 65536);
    gemm_nt<1, true,  false><<<convGrid, 256>>>(x, 259, 0, tk_w, 0, tk_b, nullptr, nullptr, 0, k, 65536);
    gemm_nt<2, true,  false><<<convGrid, 256>>>(x, 259, 0, tv_w, 0, tv_b, nullptr, nullptr, 0, v, 65536);
    gemm_tn<<<tnGrid, 256>>>(q, k, attn);
    softmax_rows<<<512, 256>>>(attn);
    // x2 = t_gamma*out2 + x1  (x1 read + x2 written by the same thread/element)
    gemm_nt<0, false, true><<<outGrid, 256>>>(v, 256, 4096L * 256, attn, 65536L,
                                              nullptr, t_gamma, out, 256, out, 4096);
}

// round 5
// speedup vs baseline: 1.8299x; 1.8299x over previous
#include <cuda_runtime.h>
#include <cstdint>

// ===========================================================================
// LossRecovery via mma.sync tf32 (sm_80-portable ISA; tcgen05 not available
// at the harness's compute_103 target). 3xTF32 on q/k/score paths.
//
// Unified NT GEMM: C[m,n] = sum_k A[m,k] * B[n,k]
//   AMODE 0: plain rows   1: spatial-transpose row gather (tk)
//   AMODE 2: v2 reshape gather (tv out-GEMM; d2 == d identity, z/ch remap)
//   EMODE 0: plain + bias (v convs)        1: transposed [c][s] + bias (q/k)
//   EMODE 2: plain (scores)                3: gamma*acc + res (out-GEMMs)
// ===========================================================================

__device__ float g_q[16L * 256 * 4096];      // qT [z][c][s]
__device__ float g_k[16L * 256 * 4096];      // kT [z][d][s]
__device__ float g_v[16L * 4096 * 256];      // v  [z][s][d]
__device__ float g_attn[16L * 256 * 256];

__device__ __forceinline__ float tr32(float a) {
    return __uint_as_float(__float_as_uint(a) & 0xFFFFE000u);
}

template <bool THREE, int AMODE, bool AVEC, int EMODE, int NT>
__global__ __launch_bounds__(256, 1) void gemm_tc(
    const float* __restrict__ A, int lda, long aZ,
    const float* __restrict__ B, int ldb, long bZ,
    int Kdim,
    const float* __restrict__ bias,
    const float* __restrict__ gammaPtr,
    const float* __restrict__ res, int ldr,
    float* __restrict__ out)
{
    extern __shared__ float sm[];
    constexpr int ALD = 36;
    constexpr int ATILE = 128 * ALD;
    constexpr int BTILE = NT * ALD;
    float* sAh = sm;
    float* sAl = THREE ? (sm + ATILE) : sm;
    float* sBh = sm + (THREE ? 2 : 1) * ATILE;
    float* sBl = THREE ? (sBh + BTILE) : sBh;

    const int tid = threadIdx.x;
    const int wid = tid >> 5, lane = tid & 31;
    const int grp = lane >> 2, tig = lane & 3;
    const int row0 = blockIdx.x * 128, col0 = blockIdx.y * NT, z = blockIdx.z;

    constexpr int MI = (NT == 128) ? 4 : 2;
    const int m_base = (NT == 128) ? ((wid >> 2) * 64) : ((wid >> 1) * 32);
    const int n_base = (NT == 128) ? ((wid & 3) * 32) : ((wid & 1) * 32);

    float acc[MI][4][4];
#pragma unroll
    for (int mi = 0; mi < MI; mi++)
#pragma unroll
        for (int ni = 0; ni < 4; ni++)
#pragma unroll
            for (int e = 0; e < 4; e++) acc[mi][ni][e] = 0.f;

    // ---- A loader setup: thread -> row ar, 16-col half ha ----
    const int ar = tid >> 1, ha = (tid & 1) * 16;
    const float* ap = nullptr;
    const float* base0 = nullptr;
    if (AMODE == 0) {
        ap = A + (long)z * aZ + (long)(row0 + ar) * lda;
    } else if (AMODE == 1) {
        const int grow = row0 + ar;
        const int t = grow & 4095;
        const int s = ((t & 63) << 6) | (t >> 6);
        ap = A + ((long)(grow >> 12) * 4096 + s) * (long)lda;
    } else {
        const int bq = z >> 3, chHi = z & 7;
        base0 = A + ((long)(bq * 8) * 4096 + (row0 + ar)) * 256 + chHi * 32;
    }

    // ---- B loader setup ----
    constexpr int TPR = 256 / NT;      // threads per B row
    constexpr int NF = 32 / TPR;       // floats per thread
    const int bn = tid / TPR, hb = (tid % TPR) * NF;
    const float* bp = B + (long)z * bZ + (long)(col0 + bn) * ldb + hb;

    const int nChunks = Kdim >> 5;
    for (int kc = 0; kc < nChunks; kc++) {
        const int kbase = kc << 5;
        // ---- load A 128x32 ----
        float va[16];
        if (AMODE == 2) {
#pragma unroll
            for (int i = 0; i < 16; i++) {
                int d = kbase + ha + i;
                va[i] = base0[(long)(d & 7) * 1048576 + (d >> 3)];
            }
        } else if (AVEC) {
            const float4* p = (const float4*)(ap + kbase + ha);
#pragma unroll
            for (int j = 0; j < 4; j++) {
                float4 f = p[j];
                va[4 * j] = f.x; va[4 * j + 1] = f.y; va[4 * j + 2] = f.z; va[4 * j + 3] = f.w;
            }
        } else {
#pragma unroll
            for (int i = 0; i < 16; i++) va[i] = ap[kbase + ha + i];
        }
#pragma unroll
        for (int i = 0; i < 16; i++) {
            const int off = ar * ALD + ha + i;
            if (THREE) {
                float hi = tr32(va[i]);
                sAh[off] = hi;
                sAl[off] = tr32(va[i] - hi);
            } else sAh[off] = va[i];
        }
        // ---- load B NTx32 ----
        {
            const float4* p = (const float4*)(bp + kbase);
            float vb[NF];
#pragma unroll
            for (int j = 0; j < NF / 4; j++) {
                float4 f = p[j];
                vb[4 * j] = f.x; vb[4 * j + 1] = f.y; vb[4 * j + 2] = f.z; vb[4 * j + 3] = f.w;
            }
#pragma unroll
            for (int i = 0; i < NF; i++) {
                const int off = bn * ALD + hb + i;
                if (THREE) {
                    float hi = tr32(vb[i]);
                    sBh[off] = hi;
                    sBl[off] = tr32(vb[i] - hi);
                } else sBh[off] = vb[i];
            }
        }
        __syncthreads();

        // ---- compute: 4 ksteps x (1 or 3) passes ----
#pragma unroll
        for (int ks = 0; ks < 4; ks++) {
            const int kk = ks * 8;
            constexpr int NP = THREE ? 3 : 1;
#pragma unroll
            for (int p = 0; p < NP; p++) {
                const float* aS = (p == 2) ? sAl : sAh;
                const float* bS = (p == 1) ? sBl : sBh;
                uint32_t bf[4][2];
#pragma unroll
                for (int ni = 0; ni < 4; ni++) {
                    const int nb = n_base + ni * 8 + grp;
                    bf[ni][0] = __float_as_uint(bS[nb * ALD + kk + tig]);
                    bf[ni][1] = __float_as_uint(bS[nb * ALD + kk + tig + 4]);
                }
#pragma unroll
                for (int mi = 0; mi < MI; mi++) {
                    const int mb = m_base + mi * 16;
                    uint32_t a0 = __float_as_uint(aS[(mb + grp) * ALD + kk + tig]);
                    uint32_t a1 = __float_as_uint(aS[(mb + grp + 8) * ALD + kk + tig]);
                    uint32_t a2 = __float_as_uint(aS[(mb + grp) * ALD + kk + tig + 4]);
                    uint32_t a3 = __float_as_uint(aS[(mb + grp + 8) * ALD + kk + tig + 4]);
#pragma unroll
                    for (int ni = 0; ni < 4; ni++) {
                        asm volatile(
                            "mma.sync.aligned.m16n8k8.row.col.f32.tf32.tf32.f32 "
                            "{%0,%1,%2,%3},{%4,%5,%6,%7},{%8,%9},{%0,%1,%2,%3};"
                            : "+f"(acc[mi][ni][0]), "+f"(acc[mi][ni][1]),
                              "+f"(acc[mi][ni][2]), "+f"(acc[mi][ni][3])
                            : "r"(a0), "r"(a1), "r"(a2), "r"(a3),
                              "r"(bf[ni][0]), "r"(bf[ni][1]));
                    }
                }
            }
        }
        __syncthreads();
    }

    // ---- epilogues ----
    if (EMODE == 1) {
        // stage C 128x128 into smem (stride 133), then coalesced transposed store
        float* sC = sm;
#pragma unroll
        for (int mi = 0; mi < MI; mi++)
#pragma unroll
            for (int ni = 0; ni < 4; ni++) {
                const int r0 = m_base + mi * 16 + grp;
                const int cb = n_base + ni * 8 + 2 * tig;
                sC[r0 * 133 + cb] = acc[mi][ni][0];
                sC[r0 * 133 + cb + 1] = acc[mi][ni][1];
                sC[(r0 + 8) * 133 + cb] = acc[mi][ni][2];
                sC[(r0 + 8) * 133 + cb + 1] = acc[mi][ni][3];
            }
        __syncthreads();
        const int rw = tid & 127, g2 = tid >> 7;
        const int bl = row0 >> 12, sb = row0 & 4095;
        for (int cp = 0; cp < 64; cp++) {
            const int col = cp * 2 + g2;
            const int ch = col0 + col;
            const float val = sC[rw * 133 + col] + __ldg(&bias[ch]);
            out[((long)bl * 256 + ch) * 4096 + sb + rw] = val;
        }
    } else {
        float gamma = 0.f;
        if (EMODE == 3) gamma = __ldg(gammaPtr);
#pragma unroll
        for (int mi = 0; mi < MI; mi++)
#pragma unroll
            for (int ni = 0; ni < 4; ni++) {
                const int r0g = m_base + mi * 16 + grp;
                const int cb = n_base + ni * 8 + 2 * tig;
                const int c = col0 + cb;
#pragma unroll
                for (int half = 0; half < 2; half++) {
                    const int r = row0 + r0g + half * 8;
                    float v0 = acc[mi][ni][2 * half];
                    float v1 = acc[mi][ni][2 * half + 1];
                    if (EMODE == 0) {
                        v0 += __ldg(&bias[c]);
                        v1 += __ldg(&bias[c + 1]);
                        float2 st = {v0, v1};
                        *(float2*)(out + (long)r * 256 + c) = st;
                    } else if (EMODE == 2) {
                        float2 st = {v0, v1};
                        *(float2*)(out + (long)z * 65536 + (long)r * 256 + c) = st;
                    } else {
                        const long rr = (long)z * 4096 + r;
                        v0 = gamma * v0 + res[rr * (long)ldr + c];
                        v1 = gamma * v1 + res[rr * (long)ldr + c + 1];
                        float2 st = {v0, v1};
                        *(float2*)(out + rr * 256 + c) = st;
                    }
                }
            }
    }
}

// ---------------- softmax: 16*256 rows of 256 ----------------
__global__ __launch_bounds__(256) void softmax_rows(float* __restrict__ data) {
    const int row = blockIdx.x * 8 + (threadIdx.x >> 5);
    const int lane = threadIdx.x & 31;
    float* p = data + (long)row * 256;
    float vv[8];
    float m = -1e30f;
#pragma unroll
    for (int i = 0; i < 8; i++) { vv[i] = p[i * 32 + lane]; m = fmaxf(m, vv[i]); }
#pragma unroll
    for (int o = 16; o; o >>= 1) m = fmaxf(m, __shfl_xor_sync(0xffffffffu, m, o));
    float s = 0.f;
#pragma unroll
    for (int i = 0; i < 8; i++) { vv[i] = __expf(vv[i] - m); s += vv[i]; }
#pragma unroll
    for (int o = 16; o; o >>= 1) s += __shfl_xor_sync(0xffffffffu, s, o);
    const float inv = 1.f / s;
#pragma unroll
    for (int i = 0; i < 8; i++) p[i * 32 + lane] = vv[i] * inv;
}

// ---------------- launch ----------------
extern "C" void kernel_launch(void* const* d_in, const int* in_sizes, int n_in,
                              void* d_out, int out_size)
{
    const float* x    = (const float*)d_in[0];
    const float* sq_w = (const float*)d_in[3];
    const float* sq_b = (const float*)d_in[4];
    const float* sk_w = (const float*)d_in[5];
    const float* sk_b = (const float*)d_in[6];
    const float* sv_w = (const float*)d_in[7];
    const float* sv_b = (const float*)d_in[8];
    const float* tq_w = (const float*)d_in[9];
    const float* tq_b = (const float*)d_in[10];
    const float* tk_w = (const float*)d_in[11];
    const float* tk_b = (const float*)d_in[12];
    const float* tv_w = (const float*)d_in[13];
    const float* tv_b = (const float*)d_in[14];
    const float* s_gamma = (const float*)d_in[15];
    const float* t_gamma = (const float*)d_in[16];
    float* out = (float*)d_out;

    float *q, *k, *v, *attn;
    cudaGetSymbolAddress((void**)&q, g_q);
    cudaGetSymbolAddress((void**)&k, g_k);
    cudaGetSymbolAddress((void**)&v, g_v);
    cudaGetSymbolAddress((void**)&attn, g_attn);

    // instantiations
    auto convA  = gemm_tc<true, 0, false, 1, 128>;   // sq, sk (x, lda 259)
    auto convQ2 = gemm_tc<true, 0, true, 1, 128>;    // tq (x1, lda 256)
    auto convKG = gemm_tc<true, 1, false, 1, 128>;   // tk (gathered x)
    auto convV  = gemm_tc<false, 0, false, 0, 128>;  // sv, tv
    auto scoreK = gemm_tc<true, 0, true, 2, 64>;     // scores
    auto outV1  = gemm_tc<false, 0, true, 3, 128>;   // out spatial
    auto outV2  = gemm_tc<false, 2, false, 3, 128>;  // out temporal (v2 gather)

    cudaFuncSetAttribute(convA, cudaFuncAttributeMaxDynamicSharedMemorySize, 73728);
    cudaFuncSetAttribute(convQ2, cudaFuncAttributeMaxDynamicSharedMemorySize, 73728);
    cudaFuncSetAttribute(convKG, cudaFuncAttributeMaxDynamicSharedMemorySize, 73728);
    cudaFuncSetAttribute(convV, cudaFuncAttributeMaxDynamicSharedMemorySize, 36864);
    cudaFuncSetAttribute(scoreK, cudaFuncAttributeMaxDynamicSharedMemorySize, 55296);
    cudaFuncSetAttribute(outV1, cudaFuncAttributeMaxDynamicSharedMemorySize, 36864);
    cudaFuncSetAttribute(outV2, cudaFuncAttributeMaxDynamicSharedMemorySize, 36864);

    const dim3 cg(512, 2, 1);
    const dim3 sg(2, 4, 16);
    const dim3 og(32, 2, 16);

    // ---- spatial ----
    convA<<<cg, 256, 73728>>>(x, 259, 0, sq_w, 256, 0, 256, sq_b, nullptr, nullptr, 0, q);
    convA<<<cg, 256, 73728>>>(x, 259, 0, sk_w, 256, 0, 256, sk_b, nullptr, nullptr, 0, k);
    convV<<<cg, 256, 36864>>>(x, 259, 0, sv_w, 256, 0, 256, sv_b, nullptr, nullptr, 0, v);
    scoreK<<<sg, 256, 55296>>>(q, 4096, 1048576L, k, 4096, 1048576L, 4096,
                               nullptr, nullptr, nullptr, 0, attn);
    softmax_rows<<<512, 256>>>(attn);
    outV1<<<og, 256, 36864>>>(v, 256, 1048576L, attn, 256, 65536L, 256,
                              nullptr, s_gamma, x, 259, out);

    // ---- temporal ----
    convQ2<<<cg, 256, 73728>>>(out, 256, 0, tq_w, 256, 0, 256, tq_b, nullptr, nullptr, 0, q);
    convKG<<<cg, 256, 73728>>>(x, 259, 0, tk_w, 256, 0, 256, tk_b, nullptr, nullptr, 0, k);
    convV<<<cg, 256, 36864>>>(x, 259, 0, tv_w, 256, 0, 256, tv_b, nullptr, nullptr, 0, v);
    scoreK<<<sg, 256, 55296>>>(q, 4096, 1048576L, k, 4096, 1048576L, 4096,
                               nullptr, nullptr, nullptr, 0, attn);
    softmax_rows<<<512, 256>>>(attn);
    outV2<<<og, 256, 36864>>>(v, 0, 0, attn, 256, 65536L, 256,
                              nullptr, t_gamma, out, 256, out);
}

// round 6
// speedup vs baseline: 2.1352x; 1.1668x over previous
#include <cuda_runtime.h>
#include <cstdint>

// ===========================================================================
// LossRecovery via mma.sync tf32, cp.async double-buffered, consumer-side
// 3xTF32 split (q/k convs + scores), split-K=2 scores folded into softmax.
//
// Unified NT GEMM: C[m,n] = sum_k A[m,k] * B[n,k]
//   AMODE 0: plain rows   1: spatial-transpose row gather (tk)
//   AMODE 2: v2 reshape gather (tv out-GEMM)
//   EMODE 0: plain+bias   1: transposed [c][s]+bias   2: scores (split-K)
//   EMODE 3: gamma*acc + res
// ===========================================================================

__device__ float g_q[16L * 256 * 4096];      // qT [z][c][s]
__device__ float g_k[16L * 256 * 4096];      // kT [z][d][s]
__device__ float g_v[16L * 4096 * 256];      // v  [z][s][d]
__device__ float g_attn[32L * 256 * 256];    // two split-K halves

#define CP16(dst, src) asm volatile("cp.async.cg.shared.global [%0], [%1], 16;\n" :: "r"(dst), "l"(src))
#define CP4(dst, src)  asm volatile("cp.async.ca.shared.global [%0], [%1], 4;\n"  :: "r"(dst), "l"(src))
#define CPCOMMIT()     asm volatile("cp.async.commit_group;\n" ::: "memory")
#define CPWAIT(n)      asm volatile("cp.async.wait_group %0;\n" :: "n"(n) : "memory")

__device__ __forceinline__ void split32(float v, uint32_t& h, uint32_t& l) {
    uint32_t hu = __float_as_uint(v) & 0xFFFFE000u;
    h = hu;
    l = __float_as_uint(v - __uint_as_float(hu));
}

#define MMA_T(ac, a0, a1, a2, a3, b0, b1) \
    asm volatile("mma.sync.aligned.m16n8k8.row.col.f32.tf32.tf32.f32 " \
        "{%0,%1,%2,%3},{%4,%5,%6,%7},{%8,%9},{%0,%1,%2,%3};" \
        : "+f"((ac)[0]), "+f"((ac)[1]), "+f"((ac)[2]), "+f"((ac)[3]) \
        : "r"(a0), "r"(a1), "r"(a2), "r"(a3), "r"(b0), "r"(b1))

template <bool THREE, int AMODE, bool AVEC, int EMODE, int NT>
__global__ __launch_bounds__(256, (NT == 64) ? 2 : 1) void gemm_tc(
    const float* __restrict__ A, int lda, long aZ,
    const float* __restrict__ B, int ldb, long bZ,
    int Kdim,
    const float* __restrict__ bias,
    const float* __restrict__ gammaPtr,
    const float* __restrict__ res, int ldr,
    float* __restrict__ out)
{
    extern __shared__ float sm[];
    constexpr int ALD = 36;
    constexpr int STAGE = (128 + NT) * ALD;
    const uint32_t sbB = (uint32_t)__cvta_generic_to_shared(sm);

    const int tid = threadIdx.x;
    const int wid = tid >> 5, lane = tid & 31;
    const int grp = lane >> 2, tig = lane & 3;
    const int row0 = blockIdx.x * 128, col0 = blockIdx.y * NT;
    const int z = blockIdx.z;
    int zA = z;
    long koff = 0;
    if (EMODE == 2) { zA = z & 15; koff = (long)(z >> 4) * Kdim; }

    constexpr int MI = (NT == 128) ? 4 : 2;
    const int m_base = (NT == 128) ? ((wid >> 2) * 64) : ((wid >> 1) * 32);
    const int n_base = (NT == 128) ? ((wid & 3) * 32) : ((wid & 1) * 32);

    float acc[MI][4][4];
#pragma unroll
    for (int mi = 0; mi < MI; mi++)
#pragma unroll
        for (int ni = 0; ni < 4; ni++)
#pragma unroll
            for (int e = 0; e < 4; e++) acc[mi][ni][e] = 0.f;

    // ---- A loader setup ----
    const int ar = tid >> 1, ha = (tid & 1) * 16;
    const float* ap = nullptr;
    const float* base0 = nullptr;
    if (AMODE == 0) {
        ap = A + (long)zA * aZ + (long)(row0 + ar) * lda + koff;
    } else if (AMODE == 1) {
        const int grow = row0 + ar;
        const int t = grow & 4095;
        const int s = ((t & 63) << 6) | (t >> 6);
        ap = A + ((long)(grow >> 12) * 4096 + s) * (long)lda;
    } else {
        const int bq = z >> 3, chHi = z & 7;
        base0 = A + ((long)(bq * 8) * 4096 + (row0 + ar)) * 256 + chHi * 32;
    }
    // ---- B loader setup ----
    constexpr int TPR = 256 / NT, NF = 32 / TPR;
    const int bn = tid / TPR, hb = (tid % TPR) * NF;
    const float* bp = B + (long)zA * bZ + (long)(col0 + bn) * ldb + hb + koff;

    const int nCh = Kdim >> 5;

    auto load_tile = [&](int kc, int s) {
        const int kb = kc << 5;
        const uint32_t aD = sbB + (uint32_t)(s * STAGE + ar * ALD + ha) * 4u;
        if (AMODE == 2) {
#pragma unroll
            for (int i = 0; i < 16; i++) {
                const int d = kb + ha + i;
                CP4(aD + i * 4u, base0 + (long)(d & 7) * 1048576 + (d >> 3));
            }
        } else if (AVEC) {
#pragma unroll
            for (int j = 0; j < 4; j++) CP16(aD + j * 16u, ap + kb + ha + 4 * j);
        } else {
#pragma unroll
            for (int i = 0; i < 16; i++) CP4(aD + i * 4u, ap + kb + ha + i);
        }
        const uint32_t bD = sbB + (uint32_t)(s * STAGE + 128 * ALD + bn * ALD + hb) * 4u;
#pragma unroll
        for (int j = 0; j < NF / 4; j++) CP16(bD + j * 16u, bp + kb + 4 * j);
    };

    load_tile(0, 0);
    CPCOMMIT();

    for (int kc = 0; kc < nCh; kc++) {
        const int s = kc & 1;
        if (kc + 1 < nCh) {
            load_tile(kc + 1, (kc + 1) & 1);
            CPCOMMIT();
            CPWAIT(1);
        } else {
            CPWAIT(0);
        }
        __syncthreads();

        const float* sA = sm + s * STAGE;
        const float* sB = sA + 128 * ALD;
#pragma unroll
        for (int ks = 0; ks < 4; ks++) {
            const int kk = ks * 8;
            uint32_t bh[4][2], blo[4][2];
#pragma unroll
            for (int ni = 0; ni < 4; ni++) {
                const int nb = n_base + ni * 8 + grp;
                const float b0 = sB[nb * ALD + kk + tig];
                const float b1 = sB[nb * ALD + kk + tig + 4];
                if (THREE) {
                    split32(b0, bh[ni][0], blo[ni][0]);
                    split32(b1, bh[ni][1], blo[ni][1]);
                } else {
                    bh[ni][0] = __float_as_uint(b0);
                    bh[ni][1] = __float_as_uint(b1);
                }
            }
#pragma unroll
            for (int mi = 0; mi < MI; mi++) {
                const int mb = m_base + mi * 16;
                const float a0 = sA[(mb + grp) * ALD + kk + tig];
                const float a1 = sA[(mb + grp + 8) * ALD + kk + tig];
                const float a2 = sA[(mb + grp) * ALD + kk + tig + 4];
                const float a3 = sA[(mb + grp + 8) * ALD + kk + tig + 4];
                uint32_t ah[4], al[4];
                if (THREE) {
                    split32(a0, ah[0], al[0]); split32(a1, ah[1], al[1]);
                    split32(a2, ah[2], al[2]); split32(a3, ah[3], al[3]);
                } else {
                    ah[0] = __float_as_uint(a0); ah[1] = __float_as_uint(a1);
                    ah[2] = __float_as_uint(a2); ah[3] = __float_as_uint(a3);
                }
#pragma unroll
                for (int ni = 0; ni < 4; ni++)
                    MMA_T(acc[mi][ni], ah[0], ah[1], ah[2], ah[3], bh[ni][0], bh[ni][1]);
                if (THREE) {
#pragma unroll
                    for (int ni = 0; ni < 4; ni++)
                        MMA_T(acc[mi][ni], ah[0], ah[1], ah[2], ah[3], blo[ni][0], blo[ni][1]);
#pragma unroll
                    for (int ni = 0; ni < 4; ni++)
                        MMA_T(acc[mi][ni], al[0], al[1], al[2], al[3], bh[ni][0], bh[ni][1]);
                }
            }
        }
        __syncthreads();
    }

    // ---- epilogues ----
    if (EMODE == 1) {
        float* sC = sm;
#pragma unroll
        for (int mi = 0; mi < MI; mi++)
#pragma unroll
            for (int ni = 0; ni < 4; ni++) {
                const int r0 = m_base + mi * 16 + grp;
                const int cb = n_base + ni * 8 + 2 * tig;
                sC[r0 * 133 + cb] = acc[mi][ni][0];
                sC[r0 * 133 + cb + 1] = acc[mi][ni][1];
                sC[(r0 + 8) * 133 + cb] = acc[mi][ni][2];
                sC[(r0 + 8) * 133 + cb + 1] = acc[mi][ni][3];
            }
        __syncthreads();
        const int rw = tid & 127, g2 = tid >> 7;
        const int bl = row0 >> 12, sb = row0 & 4095;
        for (int cp = 0; cp < 64; cp++) {
            const int col = cp * 2 + g2;
            const int ch = col0 + col;
            const float val = sC[rw * 133 + col] + __ldg(&bias[ch]);
            out[((long)bl * 256 + ch) * 4096 + sb + rw] = val;
        }
    } else {
        float gamma = 0.f;
        if (EMODE == 3) gamma = __ldg(gammaPtr);
#pragma unroll
        for (int mi = 0; mi < MI; mi++)
#pragma unroll
            for (int ni = 0; ni < 4; ni++) {
                const int r0g = m_base + mi * 16 + grp;
                const int cb = n_base + ni * 8 + 2 * tig;
                const int c = col0 + cb;
#pragma unroll
                for (int half = 0; half < 2; half++) {
                    const int r = row0 + r0g + half * 8;
                    float v0 = acc[mi][ni][2 * half];
                    float v1 = acc[mi][ni][2 * half + 1];
                    if (EMODE == 0) {
                        v0 += __ldg(&bias[c]);
                        v1 += __ldg(&bias[c + 1]);
                        float2 st = {v0, v1};
                        *(float2*)(out + (long)r * 256 + c) = st;
                    } else if (EMODE == 2) {
                        float2 st = {v0, v1};
                        *(float2*)(out + (long)z * 65536 + (long)r * 256 + c) = st;
                    } else {
                        const long rr = (long)z * 4096 + r;
                        v0 = gamma * v0 + res[rr * (long)ldr + c];
                        v1 = gamma * v1 + res[rr * (long)ldr + c + 1];
                        float2 st = {v0, v1};
                        *(float2*)(out + rr * 256 + c) = st;
                    }
                }
            }
    }
}

// ---------------- softmax over split-K halves: 4096 rows of 256 ----------------
__global__ __launch_bounds__(256) void softmax_rows(float* __restrict__ data) {
    const int row = blockIdx.x * 8 + (threadIdx.x >> 5);
    const int lane = threadIdx.x & 31;
    float* p0 = data + (long)row * 256;
    const float* p1 = p0 + 1048576L;   // second split-K half (16 z-slices later)
    float vv[8];
    float m = -1e30f;
#pragma unroll
    for (int i = 0; i < 8; i++) {
        vv[i] = p0[i * 32 + lane] + p1[i * 32 + lane];
        m = fmaxf(m, vv[i]);
    }
#pragma unroll
    for (int o = 16; o; o >>= 1) m = fmaxf(m, __shfl_xor_sync(0xffffffffu, m, o));
    float s = 0.f;
#pragma unroll
    for (int i = 0; i < 8; i++) { vv[i] = __expf(vv[i] - m); s += vv[i]; }
#pragma unroll
    for (int o = 16; o; o >>= 1) s += __shfl_xor_sync(0xffffffffu, s, o);
    const float inv = 1.f / s;
#pragma unroll
    for (int i = 0; i < 8; i++) p0[i * 32 + lane] = vv[i] * inv;
}

// ---------------- launch ----------------
extern "C" void kernel_launch(void* const* d_in, const int* in_sizes, int n_in,
                              void* d_out, int out_size)
{
    const float* x    = (const float*)d_in[0];
    const float* sq_w = (const float*)d_in[3];
    const float* sq_b = (const float*)d_in[4];
    const float* sk_w = (const float*)d_in[5];
    const float* sk_b = (const float*)d_in[6];
    const float* sv_w = (const float*)d_in[7];
    const float* sv_b = (const float*)d_in[8];
    const float* tq_w = (const float*)d_in[9];
    const float* tq_b = (const float*)d_in[10];
    const float* tk_w = (const float*)d_in[11];
    const float* tk_b = (const float*)d_in[12];
    const float* tv_w = (const float*)d_in[13];
    const float* tv_b = (const float*)d_in[14];
    const float* s_gamma = (const float*)d_in[15];
    const float* t_gamma = (const float*)d_in[16];
    float* out = (float*)d_out;

    float *q, *k, *v, *attn;
    cudaGetSymbolAddress((void**)&q, g_q);
    cudaGetSymbolAddress((void**)&k, g_k);
    cudaGetSymbolAddress((void**)&v, g_v);
    cudaGetSymbolAddress((void**)&attn, g_attn);

    auto convA  = gemm_tc<true, 0, false, 1, 128>;   // sq, sk (x, lda 259)
    auto convQ2 = gemm_tc<true, 0, true, 1, 128>;    // tq (x1, lda 256)
    auto convKG = gemm_tc<true, 1, false, 1, 128>;   // tk (gathered x)
    auto convV  = gemm_tc<false, 0, false, 0, 128>;  // sv, tv
    auto scoreK = gemm_tc<true, 0, true, 2, 64>;     // scores (split-K=2)
    auto outV1  = gemm_tc<false, 0, true, 3, 128>;   // out spatial
    auto outV2  = gemm_tc<false, 2, false, 3, 128>;  // out temporal (v2 gather)

    const int SM128 = 2 * (128 + 128) * 36 * 4;   // 73728
    const int SM64  = 2 * (128 + 64) * 36 * 4;    // 55296
    cudaFuncSetAttribute(convA,  cudaFuncAttributeMaxDynamicSharedMemorySize, SM128);
    cudaFuncSetAttribute(convQ2, cudaFuncAttributeMaxDynamicSharedMemorySize, SM128);
    cudaFuncSetAttribute(convKG, cudaFuncAttributeMaxDynamicSharedMemorySize, SM128);
    cudaFuncSetAttribute(convV,  cudaFuncAttributeMaxDynamicSharedMemorySize, SM128);
    cudaFuncSetAttribute(scoreK, cudaFuncAttributeMaxDynamicSharedMemorySize, SM64);
    cudaFuncSetAttribute(outV1,  cudaFuncAttributeMaxDynamicSharedMemorySize, SM128);
    cudaFuncSetAttribute(outV2,  cudaFuncAttributeMaxDynamicSharedMemorySize, SM128);

    const dim3 cg(512, 2, 1);
    const dim3 sg(2, 4, 32);    // split-K=2 -> 32 z-slices
    const dim3 og(32, 2, 16);

    // ---- spatial ----
    convA<<<cg, 256, SM128>>>(x, 259, 0, sq_w, 256, 0, 256, sq_b, nullptr, nullptr, 0, q);
    convA<<<cg, 256, SM128>>>(x, 259, 0, sk_w, 256, 0, 256, sk_b, nullptr, nullptr, 0, k);
    convV<<<cg, 256, SM128>>>(x, 259, 0, sv_w, 256, 0, 256, sv_b, nullptr, nullptr, 0, v);
    scoreK<<<sg, 256, SM64>>>(q, 4096, 1048576L, k, 4096, 1048576L, 2048,
                              nullptr, nullptr, nullptr, 0, attn);
    softmax_rows<<<512, 256>>>(attn);
    outV1<<<og, 256, SM128>>>(v, 256, 1048576L, attn, 256, 65536L, 256,
                              nullptr, s_gamma, x, 259, out);

    // ---- temporal ----
    convQ2<<<cg, 256, SM128>>>(out, 256, 0, tq_w, 256, 0, 256, tq_b, nullptr, nullptr, 0, q);
    convKG<<<cg, 256, SM128>>>(x, 259, 0, tk_w, 256, 0, 256, tk_b, nullptr, nullptr, 0, k);
    convV<<<cg, 256, SM128>>>(x, 259, 0, tv_w, 256, 0, 256, tv_b, nullptr, nullptr, 0, v);
    scoreK<<<sg, 256, SM64>>>(q, 4096, 1048576L, k, 4096, 1048576L, 2048,
                              nullptr, nullptr, nullptr, 0, attn);
    softmax_rows<<<512, 256>>>(attn);
    outV2<<<og, 256, SM128>>>(v, 0, 0, attn, 256, 65536L, 256,
                              nullptr, t_gamma, out, 256, out);
}

// round 7
// speedup vs baseline: 2.3126x; 1.0831x over previous
#include <cuda_runtime.h>
#include <cstdint>

// ===========================================================================
// LossRecovery via mma.sync tf32. 3-stage cp.async pipeline (1 sync/chunk),
// 2 CTAs/SM, consumer-side 3xTF32 split, split-K=4 scores, compacted x.
//
// Unified NT GEMM: C[m,n] = sum_k A[m,k] * B[n,k]
//   AMODE 0: plain rows   1: spatial-transpose row gather (tk)
//   AMODE 2: v2 reshape gather (tv out-GEMM)
//   EMODE 0: plain+bias   1: transposed [c][s]+bias   2: scores (split-K)
//   EMODE 3: gamma*acc + res
// ===========================================================================

__device__ float g_xc[65536L * 256];         // compacted x_s
__device__ float g_q[16L * 256 * 4096];      // qT [z][c][s]
__device__ float g_k[16L * 256 * 4096];      // kT [z][d][s]
__device__ float g_v[16L * 4096 * 256];      // v  [z][s][d]
__device__ float g_attn[64L * 65536];        // 4 split-K partials

#define CP16(dst, src) asm volatile("cp.async.cg.shared.global [%0], [%1], 16;\n" :: "r"(dst), "l"(src))
#define CP4(dst, src)  asm volatile("cp.async.ca.shared.global [%0], [%1], 4;\n"  :: "r"(dst), "l"(src))
#define CPCOMMIT()     asm volatile("cp.async.commit_group;\n" ::: "memory")
#define CPWAIT(n)      asm volatile("cp.async.wait_group %0;\n" :: "n"(n) : "memory")

__device__ __forceinline__ void split32(float v, uint32_t& h, uint32_t& l) {
    uint32_t hu = __float_as_uint(v) & 0xFFFFE000u;
    h = hu;
    l = __float_as_uint(v - __uint_as_float(hu));
}

#define MMA_T(ac, a0, a1, a2, a3, b0, b1) \
    asm volatile("mma.sync.aligned.m16n8k8.row.col.f32.tf32.tf32.f32 " \
        "{%0,%1,%2,%3},{%4,%5,%6,%7},{%8,%9},{%0,%1,%2,%3};" \
        : "+f"((ac)[0]), "+f"((ac)[1]), "+f"((ac)[2]), "+f"((ac)[3]) \
        : "r"(a0), "r"(a1), "r"(a2), "r"(a3), "r"(b0), "r"(b1))

template <bool THREE, int AMODE, int EMODE, int NT>
__global__ __launch_bounds__(256, 2) void gemm_tc(
    const float* __restrict__ A, int lda, long aZ,
    const float* __restrict__ B, int ldb, long bZ,
    int Kdim,
    const float* __restrict__ bias,
    const float* __restrict__ gammaPtr,
    const float* __restrict__ res, int ldr,
    float* __restrict__ out)
{
    extern __shared__ float sm[];
    constexpr int ALD = 36;
    constexpr int STAGE = (128 + NT) * ALD;
    const uint32_t sbB = (uint32_t)__cvta_generic_to_shared(sm);

    const int tid = threadIdx.x;
    const int wid = tid >> 5, lane = tid & 31;
    const int grp = lane >> 2, tig = lane & 3;
    const int row0 = blockIdx.x * 128, col0 = blockIdx.y * NT;
    const int z = blockIdx.z;
    int zA = z;
    long koff = 0;
    if (EMODE == 2) { zA = z & 15; koff = (long)(z >> 4) * Kdim; }

    constexpr int MI = (NT == 128) ? 4 : 2;
    const int m_base = (NT == 128) ? ((wid >> 2) * 64) : ((wid >> 1) * 32);
    const int n_base = (NT == 128) ? ((wid & 3) * 32) : ((wid & 1) * 32);

    float acc[MI][4][4];
#pragma unroll
    for (int mi = 0; mi < MI; mi++)
#pragma unroll
        for (int ni = 0; ni < 4; ni++)
#pragma unroll
            for (int e = 0; e < 4; e++) acc[mi][ni][e] = 0.f;

    // ---- A loader setup: row ar, 16-col half ha ----
    const int ar = tid >> 1, ha = (tid & 1) * 16;
    const float* ap = nullptr;
    const float* base0 = nullptr;
    if (AMODE == 0) {
        ap = A + (long)zA * aZ + (long)(row0 + ar) * lda + koff;
    } else if (AMODE == 1) {
        const int grow = row0 + ar;
        const int t = grow & 4095;
        const int s = ((t & 63) << 6) | (t >> 6);
        ap = A + ((long)(grow >> 12) * 4096 + s) * (long)lda;
    } else {
        const int bq = z >> 3, chHi = z & 7;
        base0 = A + ((long)(bq * 8) * 4096 + (row0 + ar)) * 256 + chHi * 32;
    }
    // ---- B loader setup ----
    constexpr int TPR = 256 / NT, NF = 32 / TPR;
    const int bn = tid / TPR, hb = (tid % TPR) * NF;
    const float* bp = B + (long)zA * bZ + (long)(col0 + bn) * ldb + hb + koff;

    const int nCh = Kdim >> 5;

    auto load_tile = [&](int kc, int s) {
        const int kb = kc << 5;
        const uint32_t aD = sbB + (uint32_t)(s * STAGE + ar * ALD + ha) * 4u;
        if (AMODE == 2) {
#pragma unroll
            for (int i = 0; i < 16; i++) {
                const int d = kb + ha + i;
                CP4(aD + i * 4u, base0 + (long)(d & 7) * 1048576 + (d >> 3));
            }
        } else {
#pragma unroll
            for (int j = 0; j < 4; j++) CP16(aD + j * 16u, ap + kb + ha + 4 * j);
        }
        const uint32_t bD = sbB + (uint32_t)(s * STAGE + 128 * ALD + bn * ALD + hb) * 4u;
#pragma unroll
        for (int j = 0; j < NF / 4; j++) CP16(bD + j * 16u, bp + kb + 4 * j);
    };

    // prologue: stages 0,1
    load_tile(0, 0); CPCOMMIT();
    load_tile(1, 1); CPCOMMIT();

    for (int kc = 0; kc < nCh; kc++) {
        CPWAIT(1);
        __syncthreads();
        const int ld = kc + 2;
        if (ld < nCh) load_tile(ld, ld % 3);
        CPCOMMIT();

        const float* sA = sm + (kc % 3) * STAGE;
        const float* sB = sA + 128 * ALD;
#pragma unroll
        for (int ks = 0; ks < 4; ks++) {
            const int kk = ks * 8;
            uint32_t bh[4][2], blo[4][2];
#pragma unroll
            for (int ni = 0; ni < 4; ni++) {
                const int nb = n_base + ni * 8 + grp;
                const float b0 = sB[nb * ALD + kk + tig];
                const float b1 = sB[nb * ALD + kk + tig + 4];
                if (THREE) {
                    split32(b0, bh[ni][0], blo[ni][0]);
                    split32(b1, bh[ni][1], blo[ni][1]);
                } else {
                    bh[ni][0] = __float_as_uint(b0);
                    bh[ni][1] = __float_as_uint(b1);
                }
            }
#pragma unroll
            for (int mi = 0; mi < MI; mi++) {
                const int mb = m_base + mi * 16;
                const float a0 = sA[(mb + grp) * ALD + kk + tig];
                const float a1 = sA[(mb + grp + 8) * ALD + kk + tig];
                const float a2 = sA[(mb + grp) * ALD + kk + tig + 4];
                const float a3 = sA[(mb + grp + 8) * ALD + kk + tig + 4];
                uint32_t ah[4], al[4];
                if (THREE) {
                    split32(a0, ah[0], al[0]); split32(a1, ah[1], al[1]);
                    split32(a2, ah[2], al[2]); split32(a3, ah[3], al[3]);
                } else {
                    ah[0] = __float_as_uint(a0); ah[1] = __float_as_uint(a1);
                    ah[2] = __float_as_uint(a2); ah[3] = __float_as_uint(a3);
                }
#pragma unroll
                for (int ni = 0; ni < 4; ni++)
                    MMA_T(acc[mi][ni], ah[0], ah[1], ah[2], ah[3], bh[ni][0], bh[ni][1]);
                if (THREE) {
#pragma unroll
                    for (int ni = 0; ni < 4; ni++)
                        MMA_T(acc[mi][ni], ah[0], ah[1], ah[2], ah[3], blo[ni][0], blo[ni][1]);
#pragma unroll
                    for (int ni = 0; ni < 4; ni++)
                        MMA_T(acc[mi][ni], al[0], al[1], al[2], al[3], bh[ni][0], bh[ni][1]);
                }
            }
        }
    }

    // ---- epilogues ----
    if (EMODE == 1) {
        __syncthreads();    // all compute reads of sm done before reuse as sC
        float* sC = sm;
#pragma unroll
        for (int mi = 0; mi < MI; mi++)
#pragma unroll
            for (int ni = 0; ni < 4; ni++) {
                const int r0 = m_base + mi * 16 + grp;
                const int cb = n_base + ni * 8 + 2 * tig;
                sC[r0 * 133 + cb] = acc[mi][ni][0];
                sC[r0 * 133 + cb + 1] = acc[mi][ni][1];
                sC[(r0 + 8) * 133 + cb] = acc[mi][ni][2];
                sC[(r0 + 8) * 133 + cb + 1] = acc[mi][ni][3];
            }
        __syncthreads();
        const int rw = tid & 127, g2 = tid >> 7;
        const int bl = row0 >> 12, sb = row0 & 4095;
        for (int cp = 0; cp < 64; cp++) {
            const int col = cp * 2 + g2;
            const int ch = col0 + col;
            const float val = sC[rw * 133 + col] + __ldg(&bias[ch]);
            out[((long)bl * 256 + ch) * 4096 + sb + rw] = val;
        }
    } else {
        float gamma = 0.f;
        if (EMODE == 3) gamma = __ldg(gammaPtr);
#pragma unroll
        for (int mi = 0; mi < MI; mi++)
#pragma unroll
            for (int ni = 0; ni < 4; ni++) {
                const int r0g = m_base + mi * 16 + grp;
                const int cb = n_base + ni * 8 + 2 * tig;
                const int c = col0 + cb;
#pragma unroll
                for (int half = 0; half < 2; half++) {
                    const int r = row0 + r0g + half * 8;
                    float v0 = acc[mi][ni][2 * half];
                    float v1 = acc[mi][ni][2 * half + 1];
                    if (EMODE == 0) {
                        v0 += __ldg(&bias[c]);
                        v1 += __ldg(&bias[c + 1]);
                        float2 st = {v0, v1};
                        *(float2*)(out + (long)r * 256 + c) = st;
                    } else if (EMODE == 2) {
                        float2 st = {v0, v1};
                        *(float2*)(out + (long)z * 65536 + (long)r * 256 + c) = st;
                    } else {
                        const long rr = (long)z * 4096 + r;
                        v0 = gamma * v0 + res[rr * (long)ldr + c];
                        v1 = gamma * v1 + res[rr * (long)ldr + c + 1];
                        float2 st = {v0, v1};
                        *(float2*)(out + rr * 256 + c) = st;
                    }
                }
            }
    }
}

// ---------------- compact x[..., :256] -> aligned [65536][256] ----------------
__global__ __launch_bounds__(1024) void compact_x(const float* __restrict__ x,
                                                  float* __restrict__ xc) {
    const long i = (long)blockIdx.x * 1024 + threadIdx.x;
    const long r = i >> 8;
    const int c = (int)(i & 255);
    xc[i] = x[r * 259 + c];
}

// ---------------- softmax over 4 split-K partials ----------------
__global__ __launch_bounds__(256) void softmax_rows(float* __restrict__ data) {
    const int row = blockIdx.x * 8 + (threadIdx.x >> 5);
    const int lane = threadIdx.x & 31;
    float* p0 = data + (long)row * 256;
    float vv[8];
    float m = -1e30f;
#pragma unroll
    for (int i = 0; i < 8; i++) {
        const int c = i * 32 + lane;
        vv[i] = p0[c] + p0[c + 1048576L] + p0[c + 2097152L] + p0[c + 3145728L];
        m = fmaxf(m, vv[i]);
    }
#pragma unroll
    for (int o = 16; o; o >>= 1) m = fmaxf(m, __shfl_xor_sync(0xffffffffu, m, o));
    float s = 0.f;
#pragma unroll
    for (int i = 0; i < 8; i++) { vv[i] = __expf(vv[i] - m); s += vv[i]; }
#pragma unroll
    for (int o = 16; o; o >>= 1) s += __shfl_xor_sync(0xffffffffu, s, o);
    const float inv = 1.f / s;
#pragma unroll
    for (int i = 0; i < 8; i++) p0[i * 32 + lane] = vv[i] * inv;
}

// ---------------- launch ----------------
extern "C" void kernel_launch(void* const* d_in, const int* in_sizes, int n_in,
                              void* d_out, int out_size)
{
    const float* x    = (const float*)d_in[0];
    const float* sq_w = (const float*)d_in[3];
    const float* sq_b = (const float*)d_in[4];
    const float* sk_w = (const float*)d_in[5];
    const float* sk_b = (const float*)d_in[6];
    const float* sv_w = (const float*)d_in[7];
    const float* sv_b = (const float*)d_in[8];
    const float* tq_w = (const float*)d_in[9];
    const float* tq_b = (const float*)d_in[10];
    const float* tk_w = (const float*)d_in[11];
    const float* tk_b = (const float*)d_in[12];
    const float* tv_w = (const float*)d_in[13];
    const float* tv_b = (const float*)d_in[14];
    const float* s_gamma = (const float*)d_in[15];
    const float* t_gamma = (const float*)d_in[16];
    float* out = (float*)d_out;

    float *xc, *q, *k, *v, *attn;
    cudaGetSymbolAddress((void**)&xc, g_xc);
    cudaGetSymbolAddress((void**)&q, g_q);
    cudaGetSymbolAddress((void**)&k, g_k);
    cudaGetSymbolAddress((void**)&v, g_v);
    cudaGetSymbolAddress((void**)&attn, g_attn);

    auto convA  = gemm_tc<true, 0, 1, 128>;   // sq, sk, tq (aligned rows)
    auto convKG = gemm_tc<true, 1, 1, 128>;   // tk (gathered rows of xc)
    auto convV  = gemm_tc<false, 0, 0, 128>;  // sv, tv
    auto scoreK = gemm_tc<true, 0, 2, 64>;    // scores (split-K=4)
    auto outV1  = gemm_tc<false, 0, 3, 128>;  // out spatial
    auto outV2  = gemm_tc<false, 2, 3, 128>;  // out temporal (v2 gather)

    const int SM128 = 3 * (128 + 128) * 36 * 4;   // 110592
    const int SM64  = 3 * (128 + 64) * 36 * 4;    // 82944
    cudaFuncSetAttribute(convA,  cudaFuncAttributeMaxDynamicSharedMemorySize, SM128);
    cudaFuncSetAttribute(convKG, cudaFuncAttributeMaxDynamicSharedMemorySize, SM128);
    cudaFuncSetAttribute(convV,  cudaFuncAttributeMaxDynamicSharedMemorySize, SM128);
    cudaFuncSetAttribute(scoreK, cudaFuncAttributeMaxDynamicSharedMemorySize, SM64);
    cudaFuncSetAttribute(outV1,  cudaFuncAttributeMaxDynamicSharedMemorySize, SM128);
    cudaFuncSetAttribute(outV2,  cudaFuncAttributeMaxDynamicSharedMemorySize, SM128);

    const dim3 cg(512, 2, 1);
    const dim3 sg(2, 4, 64);    // split-K=4 -> 64 z-slices
    const dim3 og(32, 2, 16);

    compact_x<<<16384, 1024>>>(x, xc);

    // ---- spatial ----
    convA<<<cg, 256, SM128>>>(xc, 256, 0, sq_w, 256, 0, 256, sq_b, nullptr, nullptr, 0, q);
    convA<<<cg, 256, SM128>>>(xc, 256, 0, sk_w, 256, 0, 256, sk_b, nullptr, nullptr, 0, k);
    convV<<<cg, 256, SM128>>>(xc, 256, 0, sv_w, 256, 0, 256, sv_b, nullptr, nullptr, 0, v);
    scoreK<<<sg, 256, SM64>>>(q, 4096, 1048576L, k, 4096, 1048576L, 1024,
                              nullptr, nullptr, nullptr, 0, attn);
    softmax_rows<<<512, 256>>>(attn);
    outV1<<<og, 256, SM128>>>(v, 256, 1048576L, attn, 256, 65536L, 256,
                              nullptr, s_gamma, xc, 256, out);

    // ---- temporal ----
    convA<<<cg, 256, SM128>>>(out, 256, 0, tq_w, 256, 0, 256, tq_b, nullptr, nullptr, 0, q);
    convKG<<<cg, 256, SM128>>>(xc, 256, 0, tk_w, 256, 0, 256, tk_b, nullptr, nullptr, 0, k);
    convV<<<cg, 256, SM128>>>(xc, 256, 0, tv_w, 256, 0, 256, tv_b, nullptr, nullptr, 0, v);
    scoreK<<<sg, 256, SM64>>>(q, 4096, 1048576L, k, 4096, 1048576L, 1024,
                              nullptr, nullptr, nullptr, 0, attn);
    softmax_rows<<<512, 256>>>(attn);
    outV2<<<og, 256, SM128>>>(v, 0, 0, attn, 256, 65536L, 256,
                              nullptr, t_gamma, out, 256, out);
}